// round 4
// baseline (speedup 1.0000x reference)
#include <cuda_runtime.h>

#define WSZ 7
#define NTOK 49           // tokens per window
#define CDIM 128
#define NH 4
#define HD 32
#define HW 448
#define NWIN 64           // windows per spatial dim
#define QKV_STRIDE 388    // 384 + 4 pad: avoids LDS bank conflicts on k/v row reads
#define LS_STRIDE 52      // 49 padded

// shared memory layout (in floats)
#define XS_OFF   0                              // 49*128 = 6272 (x tile, reused as attn_out)
#define QKV_OFF  (NTOK * CDIM)                  // 6272
#define WS_OFF   (QKV_OFF + NTOK * QKV_STRIDE)  // 6272 + 19012 = 25284 (128x128 weight tile)
#define LS_OFF   (WS_OFF + 128 * 128)           // 41668 (49x52 logits, one head)
#define BT_OFF   (LS_OFF + NTOK * LS_STRIDE)    // 44216 (bias table, 13 + pad)
#define SMEM_FLOATS (BT_OFF + 16)               // 44232
#define SMEM_BYTES  (SMEM_FLOATS * 4)           // 176928 bytes

__global__ __launch_bounds__(256, 1)
void win_attn_fused_kernel(
    const float* __restrict__ x,
    const float* __restrict__ w_qkv,
    const float* __restrict__ b_qkv,
    const float* __restrict__ w_proj,
    const float* __restrict__ b_proj,
    const float* __restrict__ bias_table,
    float* __restrict__ out)
{
    extern __shared__ float sm[];
    float* Xs  = sm + XS_OFF;    // [49][128]   x tile, later attn output (pre-proj)
    float* QK  = sm + QKV_OFF;   // [49][388]   qkv: cols 0..127=q, 128..255=k, 256..383=v
    float* Wsm = sm + WS_OFF;    // [128][128]  weight tile
    float* Ls  = sm + LS_OFF;    // [49][52]    logits / attn weights (one head)
    float* BT  = sm + BT_OFF;    // [13]        relative position bias table

    const int tid = threadIdx.x;
    const int ww  = blockIdx.x;   // window col
    const int wh  = blockIdx.y;   // window row
    const int b   = blockIdx.z;   // batch

    if (tid < 13) BT[tid] = bias_table[tid];

    // ---- Phase 0: load 49x128 x window into smem (float4, coalesced per row) ----
    const float* xbase = x + (((long)b * HW + wh * WSZ) * HW + ww * WSZ) * CDIM;
    for (int idx = tid; idx < NTOK * 32; idx += 256) {   // 1568 float4
        int n  = idx >> 5;
        int c4 = idx & 31;
        int i = n / 7, j = n - i * 7;
        float4 v = *(const float4*)(xbase + ((long)i * HW + j) * CDIM + c4 * 4);
        *(float4*)(Xs + n * CDIM + c4 * 4) = v;
    }
    __syncthreads();

    const int ty = tid >> 5;   // warp id 0..7
    const int tx = tid & 31;   // lane

    // rows handled by this thread in the register-blocked GEMMs (clamped for safe loads)
    int mrow[7];
    #pragma unroll
    for (int r = 0; r < 7; ++r) {
        int m = ty + 8 * r;
        mrow[r] = (m < NTOK) ? m : (NTOK - 1);
    }

    float acc[7][4];

    // ---- Phase 1: QKV GEMM  (49x384 = Xs[49x128] @ w_qkv[128x384] + b_qkv) ----
    for (int t = 0; t < 3; ++t) {
        const int n0 = t * 128;
        // cooperative load of W tile [128][128]
        for (int idx = tid; idx < 128 * 32; idx += 256) {  // 4096 float4
            int k  = idx >> 5;
            int c4 = idx & 31;
            *(float4*)(Wsm + k * 128 + c4 * 4) =
                *(const float4*)(w_qkv + (long)k * 384 + n0 + c4 * 4);
        }
        __syncthreads();

        #pragma unroll
        for (int r = 0; r < 7; ++r) {
            acc[r][0] = 0.f; acc[r][1] = 0.f; acc[r][2] = 0.f; acc[r][3] = 0.f;
        }
        #pragma unroll 8
        for (int k = 0; k < 128; ++k) {
            float4 bv = *(float4*)(Wsm + k * 128 + tx * 4);
            #pragma unroll
            for (int r = 0; r < 7; ++r) {
                float a = Xs[mrow[r] * CDIM + k];
                acc[r][0] += a * bv.x; acc[r][1] += a * bv.y;
                acc[r][2] += a * bv.z; acc[r][3] += a * bv.w;
            }
        }
        float4 bb = *(const float4*)(b_qkv + n0 + tx * 4);
        #pragma unroll
        for (int r = 0; r < 7; ++r) {
            int m = ty + 8 * r;
            if (m < NTOK) {
                float4 o;
                o.x = acc[r][0] + bb.x; o.y = acc[r][1] + bb.y;
                o.z = acc[r][2] + bb.z; o.w = acc[r][3] + bb.w;
                *(float4*)(QK + m * QKV_STRIDE + n0 + tx * 4) = o;
            }
        }
        __syncthreads();
    }

    // ---- Phase 2: per-head attention ----
    const float scale = 0.17677669529663687f;   // 1/sqrt(32)
    for (int h = 0; h < NH; ++h) {
        const int qo = h * HD;           // q col offset
        const int ko = 128 + h * HD;     // k col offset
        const int vo = 256 + h * HD;     // v col offset

        // 2a: logits[n][m] = scale * q_n . k_m + bias(n,m)
        for (int idx = tid; idx < NTOK * NTOK; idx += 256) {
            int n = idx / NTOK;
            int m = idx - n * NTOK;
            const float* qp = QK + n * QKV_STRIDE + qo;
            const float* kp = QK + m * QKV_STRIDE + ko;
            float s = 0.f;
            #pragma unroll
            for (int d4 = 0; d4 < 8; ++d4) {
                float4 qv = *(const float4*)(qp + d4 * 4);
                float4 kv = *(const float4*)(kp + d4 * 4);
                s += qv.x * kv.x + qv.y * kv.y + qv.z * kv.z + qv.w * kv.w;
            }
            int rn = n / 7, cn = n - rn * 7;
            int rm = m / 7, cm = m - rm * 7;
            Ls[n * LS_STRIDE + m] = s * scale + BT[rn - rm + 6] + BT[cn - cm + 6];
        }
        __syncthreads();

        // 2b: softmax, one warp per row (lane covers m and m+32)
        for (int row = ty; row < NTOK; row += 8) {
            float v0 = Ls[row * LS_STRIDE + tx];
            float v1 = (tx + 32 < NTOK) ? Ls[row * LS_STRIDE + tx + 32] : -1e30f;
            float mx = fmaxf(v0, v1);
            #pragma unroll
            for (int o = 16; o > 0; o >>= 1)
                mx = fmaxf(mx, __shfl_xor_sync(0xffffffffu, mx, o));
            float e0 = __expf(v0 - mx);
            float e1 = (tx + 32 < NTOK) ? __expf(v1 - mx) : 0.f;
            float s = e0 + e1;
            #pragma unroll
            for (int o = 16; o > 0; o >>= 1)
                s += __shfl_xor_sync(0xffffffffu, s, o);
            float inv = 1.0f / s;
            Ls[row * LS_STRIDE + tx] = e0 * inv;
            if (tx + 32 < NTOK) Ls[row * LS_STRIDE + tx + 32] = e1 * inv;
        }
        __syncthreads();

        // 2c: out_h[n][d] = sum_m attn[n][m] * v[m][d]; warp per row, lane = d
        for (int n = ty; n < NTOK; n += 8) {
            float a = 0.f;
            const float* vp = QK + vo + tx;
            const float* ap = Ls + n * LS_STRIDE;
            #pragma unroll 7
            for (int m = 0; m < NTOK; ++m) {
                a += ap[m] * vp[m * QKV_STRIDE];
            }
            Xs[n * CDIM + qo + tx] = a;   // merged-heads layout [n][h*32+d]
        }
        __syncthreads();
    }

    // ---- Phase 3: proj GEMM  out[49x128] = attn_out[49x128] @ w_proj[128x128] + b_proj ----
    for (int idx = tid; idx < 128 * 32; idx += 256) {
        int k  = idx >> 5;
        int c4 = idx & 31;
        *(float4*)(Wsm + k * 128 + c4 * 4) =
            *(const float4*)(w_proj + (long)k * 128 + c4 * 4);
    }
    __syncthreads();

    #pragma unroll
    for (int r = 0; r < 7; ++r) {
        acc[r][0] = 0.f; acc[r][1] = 0.f; acc[r][2] = 0.f; acc[r][3] = 0.f;
    }
    #pragma unroll 8
    for (int k = 0; k < 128; ++k) {
        float4 bv = *(float4*)(Wsm + k * 128 + tx * 4);
        #pragma unroll
        for (int r = 0; r < 7; ++r) {
            float a = Xs[mrow[r] * CDIM + k];
            acc[r][0] += a * bv.x; acc[r][1] += a * bv.y;
            acc[r][2] += a * bv.z; acc[r][3] += a * bv.w;
        }
    }
    {
        float4 bb = *(const float4*)(b_proj + tx * 4);
        #pragma unroll
        for (int r = 0; r < 7; ++r) {
            int m = ty + 8 * r;
            if (m < NTOK) {
                int i = m / 7, j = m - i * 7;
                float* op = out + (((long)b * HW + wh * WSZ + i) * HW + ww * WSZ + j) * CDIM
                                + tx * 4;
                float4 o;
                o.x = acc[r][0] + bb.x; o.y = acc[r][1] + bb.y;
                o.z = acc[r][2] + bb.z; o.w = acc[r][3] + bb.w;
                *(float4*)op = o;
            }
        }
    }
}

extern "C" void kernel_launch(void* const* d_in, const int* in_sizes, int n_in,
                              void* d_out, int out_size) {
    const float* x          = (const float*)d_in[0];
    const float* w_qkv      = (const float*)d_in[1];
    const float* b_qkv      = (const float*)d_in[2];
    const float* w_proj     = (const float*)d_in[3];
    const float* b_proj     = (const float*)d_in[4];
    const float* bias_table = (const float*)d_in[5];
    float* out = (float*)d_out;

    (void)in_sizes; (void)n_in; (void)out_size;

    cudaFuncSetAttribute(win_attn_fused_kernel,
                         cudaFuncAttributeMaxDynamicSharedMemorySize, SMEM_BYTES);

    dim3 grid(NWIN, NWIN, 4);   // (window col, window row, batch) = 16384 blocks
    win_attn_fused_kernel<<<grid, 256, SMEM_BYTES>>>(
        x, w_qkv, b_qkv, w_proj, b_proj, bias_table, out);
}

// round 5
// speedup vs baseline: 1.8983x; 1.8983x over previous
#include <cuda_runtime.h>

#define WSZ 7
#define NTOK 49
#define HW 448
#define NWIN 64

// smem strides (floats). A-operand buffers: stride % 32 == 4 (conflict-free A frags)
// W buffer: stride % 32 == 8 (conflict-free B frags)
#define XSTR 132
#define QSTR 388
#define WSTR 136
#define LSTR 68

#define XS_OFF 0
#define XS_SZ  (56 * XSTR)            // 7392
#define QK_OFF (XS_OFF + XS_SZ)       // 7392
#define QK_SZ  (56 * QSTR)            // 21728
#define WS_OFF (QK_OFF + QK_SZ)       // 29120
#define WS_SZ  (128 * WSTR)           // 17408
#define LS_OFF (WS_OF_ 0)
#undef LS_OFF
#define LS_OFF (WS_OFF + WS_SZ)       // 46528
#define LS_SZ  (56 * LSTR)            // 3808
#define BQ_OFF (LS_OFF + LS_SZ)       // 50336
#define BP_OFF (BQ_OFF + 384)         // 50720
#define BT_OFF (BP_OFF + 128)         // 50848
#define SMEM_FLOATS (BT_OFF + 16)     // 50864
#define SMEM_BYTES  (SMEM_FLOATS * 4) // 203456

__device__ __forceinline__ float f2tf(float f) {
    unsigned u;
    asm("cvt.rna.tf32.f32 %0, %1;" : "=r"(u) : "f"(f));
    return __uint_as_float(u);
}

__device__ __forceinline__ void mma8(float* c, const unsigned* a, unsigned b0, unsigned b1) {
    asm volatile(
        "mma.sync.aligned.m16n8k8.row.col.f32.tf32.tf32.f32 "
        "{%0,%1,%2,%3},{%4,%5,%6,%7},{%8,%9},{%0,%1,%2,%3};\n"
        : "+f"(c[0]), "+f"(c[1]), "+f"(c[2]), "+f"(c[3])
        : "r"(a[0]), "r"(a[1]), "r"(a[2]), "r"(a[3]), "r"(b0), "r"(b1));
}

#define U(x) __float_as_uint(x)

__global__ __launch_bounds__(256, 1)
void win_attn_mma_kernel(
    const float* __restrict__ x,
    const float* __restrict__ w_qkv,
    const float* __restrict__ b_qkv,
    const float* __restrict__ w_proj,
    const float* __restrict__ b_proj,
    const float* __restrict__ bias_table,
    float* __restrict__ out)
{
    extern __shared__ float sm[];
    float* Xs  = sm + XS_OFF;   // [56][132] x tile (tf32), later attn output
    float* QK  = sm + QK_OFF;   // [56][388] q|k|v (tf32)
    float* Wsm = sm + WS_OFF;   // [128][136] weight tile (tf32)
    float* Ls  = sm + LS_OFF;   // [56][68]  logits / attn
    float* BQ  = sm + BQ_OFF;   // [384] b_qkv
    float* BP  = sm + BP_OFF;   // [128] b_proj
    float* BT  = sm + BT_OFF;   // [16]  bias table (13 + zero pad)

    const int tid = threadIdx.x;
    const int ww  = blockIdx.x;
    const int wh  = blockIdx.y;
    const int bz  = blockIdx.z;

    const int tx  = tid & 31;
    const int ty  = tid >> 5;        // warp 0..7
    const int gid = tx >> 2;         // 0..7
    const int tig = tx & 3;          // 0..3
    const int wy  = ty >> 1;         // M warp group 0..3
    const int wx  = ty & 1;          // N warp group 0..1
    const int m0  = wy * 16;

    const int arow0 = m0 + gid;                       // <= 55 always
    const int arow1 = (m0 + gid + 8 > 55) ? 55 : (m0 + gid + 8);
    const int r0 = m0 + gid;
    const int r1 = m0 + gid + 8;

    // ---- Phase 0: fills ----
    if (tid < 16) BT[tid] = (tid < 13) ? bias_table[tid] : 0.f;
    for (int i = tid; i < 384; i += 256) BQ[i] = b_qkv[i];
    if (tid < 128) BP[tid] = b_proj[tid];

    const float* xbase = x + (((long)bz * HW + wh * WSZ) * HW + ww * WSZ) * 128;
    for (int idx = tid; idx < NTOK * 32; idx += 256) {
        int n = idx >> 5, c4 = idx & 31;
        int i = n / 7, j = n - i * 7;
        float4 v = *(const float4*)(xbase + ((long)i * HW + j) * 128 + c4 * 4);
        v.x = f2tf(v.x); v.y = f2tf(v.y); v.z = f2tf(v.z); v.w = f2tf(v.w);
        *(float4*)(Xs + n * XSTR + c4 * 4) = v;
    }
    // zero V rows 49..55 (padding rows feed attn@V as B operand)
    for (int idx = tid; idx < 7 * 128; idx += 256) {
        int r = 49 + (idx >> 7), c = 256 + (idx & 127);
        QK[r * QSTR + c] = 0.f;
    }
    __syncthreads();

    // ---- Phase 1: QKV GEMM (tf32 mma), 3 passes of 128 cols ----
    for (int t = 0; t < 3; ++t) {
        for (int idx = tid; idx < 128 * 32; idx += 256) {
            int k = idx >> 5, c4 = idx & 31;
            float4 g = *(const float4*)(w_qkv + (long)k * 384 + t * 128 + c4 * 4);
            g.x = f2tf(g.x); g.y = f2tf(g.y); g.z = f2tf(g.z); g.w = f2tf(g.w);
            *(float4*)(Wsm + k * WSTR + c4 * 4) = g;
        }
        __syncthreads();

        float c[8][4];
        #pragma unroll
        for (int i = 0; i < 8; ++i) { c[i][0]=0.f; c[i][1]=0.f; c[i][2]=0.f; c[i][3]=0.f; }

        #pragma unroll 4
        for (int kk = 0; kk < 16; ++kk) {
            int k0 = kk * 8;
            unsigned a[4];
            a[0] = U(Xs[arow0 * XSTR + k0 + tig]);
            a[1] = U(Xs[arow1 * XSTR + k0 + tig]);
            a[2] = U(Xs[arow0 * XSTR + k0 + tig + 4]);
            a[3] = U(Xs[arow1 * XSTR + k0 + tig + 4]);
            #pragma unroll
            for (int nt = 0; nt < 8; ++nt) {
                int nb = wx * 64 + nt * 8 + gid;
                unsigned b0 = U(Wsm[(k0 + tig) * WSTR + nb]);
                unsigned b1 = U(Wsm[(k0 + tig + 4) * WSTR + nb]);
                mma8(c[nt], a, b0, b1);
            }
        }
        // epilogue: +bias, cvt to tf32, store into QK
        #pragma unroll
        for (int nt = 0; nt < 8; ++nt) {
            int gcol = t * 128 + wx * 64 + nt * 8 + 2 * tig;
            float bb0 = BQ[gcol], bb1 = BQ[gcol + 1];
            if (r0 < NTOK) {
                float2 v; v.x = f2tf(c[nt][0] + bb0); v.y = f2tf(c[nt][1] + bb1);
                *(float2*)(QK + r0 * QSTR + gcol) = v;
            }
            if (r1 < NTOK) {
                float2 v; v.x = f2tf(c[nt][2] + bb0); v.y = f2tf(c[nt][3] + bb1);
                *(float2*)(QK + r1 * QSTR + gcol) = v;
            }
        }
        __syncthreads();
    }

    // prefetch proj weights into Wsm (free after phase 1; read only in phase 3)
    for (int idx = tid; idx < 128 * 32; idx += 256) {
        int k = idx >> 5, c4 = idx & 31;
        float4 g = *(const float4*)(w_proj + (long)k * 128 + c4 * 4);
        g.x = f2tf(g.x); g.y = f2tf(g.y); g.z = f2tf(g.z); g.w = f2tf(g.w);
        *(float4*)(Wsm + k * WSTR + c4 * 4) = g;
    }

    // ---- Phase 2: per-head attention ----
    const float scale = 0.17677669529663687f;  // 1/sqrt(32)
    const int rn0 = r0 / 7, cn0 = r0 - rn0 * 7;
    const int rn1 = r1 / 7, cn1 = r1 - rn1 * 7;

    for (int h = 0; h < 4; ++h) {
        const int qo = h * 32;
        const int ko = 128 + qo;
        const int vo = 256 + qo;

        // 2a: logits = scale * Q K^T + bias   (warp tile 16 x 32/24)
        {
            float c[4][4];
            #pragma unroll
            for (int i = 0; i < 4; ++i) { c[i][0]=0.f; c[i][1]=0.f; c[i][2]=0.f; c[i][3]=0.f; }
            const int ntmax = wx ? 3 : 4;   // cols 56..63 never used
            #pragma unroll
            for (int ks = 0; ks < 4; ++ks) {
                int k0 = ks * 8;
                unsigned a[4];
                a[0] = U(QK[arow0 * QSTR + qo + k0 + tig]);
                a[1] = U(QK[arow1 * QSTR + qo + k0 + tig]);
                a[2] = U(QK[arow0 * QSTR + qo + k0 + tig + 4]);
                a[3] = U(QK[arow1 * QSTR + qo + k0 + tig + 4]);
                for (int nt = 0; nt < ntmax; ++nt) {
                    int nb = wx * 32 + nt * 8 + gid;
                    unsigned b0 = U(QK[nb * QSTR + ko + k0 + tig]);
                    unsigned b1 = U(QK[nb * QSTR + ko + k0 + tig + 4]);
                    mma8(c[nt], a, b0, b1);
                }
            }
            for (int nt = 0; nt < ntmax; ++nt) {
                int col = wx * 32 + nt * 8 + 2 * tig;
                int rm0 = col / 7, cm0 = col - rm0 * 7;
                int col1 = col + 1;
                int rm1 = col1 / 7, cm1 = col1 - rm1 * 7;
                {
                    float2 v;
                    v.x = (col  < NTOK) ? c[nt][0] * scale + BT[rn0 - rm0 + 6] + BT[cn0 - cm0 + 6] : 0.f;
                    v.y = (col1 < NTOK) ? c[nt][1] * scale + BT[rn0 - rm1 + 6] + BT[cn0 - cm1 + 6] : 0.f;
                    *(float2*)(Ls + r0 * LSTR + col) = v;
                }
                if (r1 < 56) {
                    float2 v;
                    v.x = (col  < NTOK) ? c[nt][2] * scale + BT[rn1 - rm0 + 6] + BT[cn1 - cm0 + 6] : 0.f;
                    v.y = (col1 < NTOK) ? c[nt][3] * scale + BT[rn1 - rm1 + 6] + BT[cn1 - cm1 + 6] : 0.f;
                    *(float2*)(Ls + r1 * LSTR + col) = v;
                }
            }
        }
        __syncthreads();

        // 2b: softmax per row (warp per row); outputs tf32-rounded
        for (int row = ty; row < NTOK; row += 8) {
            float v0 = Ls[row * LSTR + tx];
            float v1 = (tx + 32 < NTOK) ? Ls[row * LSTR + tx + 32] : -1e30f;
            float mx = fmaxf(v0, v1);
            #pragma unroll
            for (int o = 16; o > 0; o >>= 1)
                mx = fmaxf(mx, __shfl_xor_sync(0xffffffffu, mx, o));
            float e0 = __expf(v0 - mx);
            float e1 = (tx + 32 < NTOK) ? __expf(v1 - mx) : 0.f;
            float s = e0 + e1;
            #pragma unroll
            for (int o = 16; o > 0; o >>= 1)
                s += __shfl_xor_sync(0xffffffffu, s, o);
            float inv = 1.0f / s;
            Ls[row * LSTR + tx] = f2tf(e0 * inv);
            if (tx + 32 < NTOK) Ls[row * LSTR + tx + 32] = f2tf(e1 * inv);
        }
        __syncthreads();

        // 2c: out_h = attn @ V   (warp tile 16 x 16, K = 56)
        {
            float c[2][4];
            #pragma unroll
            for (int i = 0; i < 2; ++i) { c[i][0]=0.f; c[i][1]=0.f; c[i][2]=0.f; c[i][3]=0.f; }
            #pragma unroll
            for (int ks = 0; ks < 7; ++ks) {
                int k0 = ks * 8;
                unsigned a[4];
                a[0] = U(Ls[arow0 * LSTR + k0 + tig]);
                a[1] = U(Ls[arow1 * LSTR + k0 + tig]);
                a[2] = U(Ls[arow0 * LSTR + k0 + tig + 4]);
                a[3] = U(Ls[arow1 * LSTR + k0 + tig + 4]);
                #pragma unroll
                for (int nt = 0; nt < 2; ++nt) {
                    int db = wx * 16 + nt * 8 + gid;
                    unsigned b0 = U(QK[(k0 + tig) * QSTR + vo + db]);
                    unsigned b1 = U(QK[(k0 + tig + 4) * QSTR + vo + db]);
                    mma8(c[nt], a, b0, b1);
                }
            }
            #pragma unroll
            for (int nt = 0; nt < 2; ++nt) {
                int col = qo + wx * 16 + nt * 8 + 2 * tig;
                if (r0 < NTOK) {
                    float2 v; v.x = f2tf(c[nt][0]); v.y = f2tf(c[nt][1]);
                    *(float2*)(Xs + r0 * XSTR + col) = v;
                }
                if (r1 < NTOK) {
                    float2 v; v.x = f2tf(c[nt][2]); v.y = f2tf(c[nt][3]);
                    *(float2*)(Xs + r1 * XSTR + col) = v;
                }
            }
        }
        __syncthreads();
    }

    // ---- Phase 3: proj GEMM, store to global (un-windowed) ----
    {
        float c[8][4];
        #pragma unroll
        for (int i = 0; i < 8; ++i) { c[i][0]=0.f; c[i][1]=0.f; c[i][2]=0.f; c[i][3]=0.f; }

        #pragma unroll 4
        for (int kk = 0; kk < 16; ++kk) {
            int k0 = kk * 8;
            unsigned a[4];
            a[0] = U(Xs[arow0 * XSTR + k0 + tig]);
            a[1] = U(Xs[arow1 * XSTR + k0 + tig]);
            a[2] = U(Xs[arow0 * XSTR + k0 + tig + 4]);
            a[3] = U(Xs[arow1 * XSTR + k0 + tig + 4]);
            #pragma unroll
            for (int nt = 0; nt < 8; ++nt) {
                int nb = wx * 64 + nt * 8 + gid;
                unsigned b0 = U(Wsm[(k0 + tig) * WSTR + nb]);
                unsigned b1 = U(Wsm[(k0 + tig + 4) * WSTR + nb]);
                mma8(c[nt], a, b0, b1);
            }
        }

        long base0 = 0, base1 = 0;
        if (r0 < NTOK) {
            int i = r0 / 7, j = r0 - (r0 / 7) * 7;
            base0 = (((long)bz * HW + wh * WSZ + i) * HW + ww * WSZ + j) * 128;
        }
        if (r1 < NTOK) {
            int i = r1 / 7, j = r1 - (r1 / 7) * 7;
            base1 = (((long)bz * HW + wh * WSZ + i) * HW + ww * WSZ + j) * 128;
        }
        #pragma unroll
        for (int nt = 0; nt < 8; ++nt) {
            int col = wx * 64 + nt * 8 + 2 * tig;
            float bb0 = BP[col], bb1 = BP[col + 1];
            if (r0 < NTOK) {
                float2 v; v.x = c[nt][0] + bb0; v.y = c[nt][1] + bb1;
                *(float2*)(out + base0 + col) = v;
            }
            if (r1 < NTOK) {
                float2 v; v.x = c[nt][2] + bb0; v.y = c[nt][3] + bb1;
                *(float2*)(out + base1 + col) = v;
            }
        }
    }
}

extern "C" void kernel_launch(void* const* d_in, const int* in_sizes, int n_in,
                              void* d_out, int out_size) {
    const float* x          = (const float*)d_in[0];
    const float* w_qkv      = (const float*)d_in[1];
    const float* b_qkv      = (const float*)d_in[2];
    const float* w_proj     = (const float*)d_in[3];
    const float* b_proj     = (const float*)d_in[4];
    const float* bias_table = (const float*)d_in[5];
    float* out = (float*)d_out;
    (void)in_sizes; (void)n_in; (void)out_size;

    cudaFuncSetAttribute(win_attn_mma_kernel,
                         cudaFuncAttributeMaxDynamicSharedMemorySize, SMEM_BYTES);

    dim3 grid(NWIN, NWIN, 4);
    win_attn_mma_kernel<<<grid, 256, SMEM_BYTES>>>(
        x, w_qkv, b_qkv, w_proj, b_proj, bias_table, out);
}

// round 7
// speedup vs baseline: 2.5176x; 1.3262x over previous
#include <cuda_runtime.h>

#define WSZ 7
#define NTOK 49
#define HW 448
#define NWIN 64

// smem strides (floats). A-operand buffers: stride % 32 == 4 (conflict-free A frags)
// W buffer: stride % 32 == 8 (conflict-free B frags)
#define XSTR 132
#define QSTR 388
#define WSTR 136
#define LSTR 68
#define LSH  (56 * LSTR)              // per-head logits block: 3808

#define XS_OFF 0
#define QK_OFF (XS_OFF + 56 * XSTR)   // 7392
#define WS_OFF (QK_OFF + 56 * QSTR)   // 29120
#define WS_SZ  (128 * WSTR)           // 17408 (>= 4*LSH = 15232, union with Ls)
#define LS_OFF WS_OFF                 // Ls[4][56][68] overlaps Wsm
#define BQ_OFF (WS_OFF + WS_SZ)       // 46528
#define BP_OFF (BQ_OFF + 384)
#define BT_OFF (BP_OFF + 128)
#define SMEM_FLOATS (BT_OFF + 16)     // 47056
#define SMEM_BYTES  (SMEM_FLOATS * 4) // 188224

__device__ __forceinline__ float f2tf(float f) {
    unsigned u;
    asm("cvt.rna.tf32.f32 %0, %1;" : "=r"(u) : "f"(f));
    return __uint_as_float(u);
}

__device__ __forceinline__ void mma8(float* c, const unsigned* a, unsigned b0, unsigned b1) {
    asm volatile(
        "mma.sync.aligned.m16n8k8.row.col.f32.tf32.tf32.f32 "
        "{%0,%1,%2,%3},{%4,%5,%6,%7},{%8,%9},{%0,%1,%2,%3};\n"
        : "+f"(c[0]), "+f"(c[1]), "+f"(c[2]), "+f"(c[3])
        : "r"(a[0]), "r"(a[1]), "r"(a[2]), "r"(a[3]), "r"(b0), "r"(b1));
}

#define U(x) __float_as_uint(x)

__global__ __launch_bounds__(512, 1)
void win_attn_mma16_kernel(
    const float* __restrict__ x,
    const float* __restrict__ w_qkv,
    const float* __restrict__ b_qkv,
    const float* __restrict__ w_proj,
    const float* __restrict__ b_proj,
    const float* __restrict__ bias_table,
    float* __restrict__ out)
{
    extern __shared__ float sm[];
    float* Xs  = sm + XS_OFF;   // [56][132] x tile (tf32), later attn output
    float* QK  = sm + QK_OFF;   // [56][388] q|k|v (tf32)
    float* Wsm = sm + WS_OFF;   // [128][136] weight tile (tf32)   (union w/ Ls)
    float* Ls  = sm + LS_OFF;   // [4][56][68] per-head logits / attn
    float* BQ  = sm + BQ_OFF;
    float* BP  = sm + BP_OFF;
    float* BT  = sm + BT_OFF;

    const int tid = threadIdx.x;
    const int ww  = blockIdx.x;
    const int wh  = blockIdx.y;
    const int bz  = blockIdx.z;

    const int tx  = tid & 31;
    const int ty  = tid >> 5;        // warp 0..15
    const int gid = tx >> 2;         // 0..7
    const int tig = tx & 3;          // 0..3

    // GEMM tiling (phases 1 & 3): 4 M-groups x 4 N-groups
    const int wyA = ty >> 2;         // 0..3 -> m16 tile
    const int wxA = ty & 3;          // 0..3 -> 32-col group
    const int m0A = wyA * 16;
    const int rA0 = m0A + gid;                          // <= 55
    const int rA1 = m0A + 8 + gid;                      // <= 63
    const int aA1 = (rA1 > 55) ? 55 : rA1;              // clamped load row

    // Attention tiling (phase 2): head = ty>>2, 4 warps per head
    const int hB  = ty >> 2;         // 0..3
    const int wy2 = (ty >> 1) & 1;   // M half (rows 0-31 / 32-63)
    const int wx2 = ty & 1;          // N half
    const int m0B = wy2 * 32;

    // ---- Phase 0: fills ----
    if (tid < 16) BT[tid] = (tid < 13) ? bias_table[tid] : 0.f;
    if (tid < 384) BQ[tid] = b_qkv[tid];
    if (tid >= 384 && tid < 512) BP[tid - 384] = b_proj[tid - 384];

    const float* xbase = x + (((long)bz * HW + wh * WSZ) * HW + ww * WSZ) * 128;
    for (int idx = tid; idx < NTOK * 32; idx += 512) {
        int n = idx >> 5, c4 = idx & 31;
        int i = n / 7, j = n - i * 7;
        float4 v = *(const float4*)(xbase + ((long)i * HW + j) * 128 + c4 * 4);
        v.x = f2tf(v.x); v.y = f2tf(v.y); v.z = f2tf(v.z); v.w = f2tf(v.w);
        *(float4*)(Xs + n * XSTR + c4 * 4) = v;
    }
    // zero V padding rows 49..55 (they feed attn@V as B operand)
    for (int idx = tid; idx < 7 * 128; idx += 512) {
        int r = 49 + (idx >> 7), c = 256 + (idx & 127);
        QK[r * QSTR + c] = 0.f;
    }
    __syncthreads();

    // ---- Phase 1: QKV GEMM (tf32 mma), 3 passes of 128 cols ----
    for (int t = 0; t < 3; ++t) {
        for (int idx = tid; idx < 128 * 32; idx += 512) {
            int k = idx >> 5, c4 = idx & 31;
            float4 g = *(const float4*)(w_qkv + (long)k * 384 + t * 128 + c4 * 4);
            g.x = f2tf(g.x); g.y = f2tf(g.y); g.z = f2tf(g.z); g.w = f2tf(g.w);
            *(float4*)(Wsm + k * WSTR + c4 * 4) = g;
        }
        __syncthreads();

        float c[4][4];
        #pragma unroll
        for (int i = 0; i < 4; ++i) { c[i][0]=0.f; c[i][1]=0.f; c[i][2]=0.f; c[i][3]=0.f; }

        #pragma unroll 4
        for (int kk = 0; kk < 16; ++kk) {
            int k0 = kk * 8;
            unsigned a[4];
            a[0] = U(Xs[rA0 * XSTR + k0 + tig]);
            a[1] = U(Xs[aA1 * XSTR + k0 + tig]);
            a[2] = U(Xs[rA0 * XSTR + k0 + tig + 4]);
            a[3] = U(Xs[aA1 * XSTR + k0 + tig + 4]);
            #pragma unroll
            for (int nt = 0; nt < 4; ++nt) {
                int nb = wxA * 32 + nt * 8 + gid;
                unsigned b0 = U(Wsm[(k0 + tig) * WSTR + nb]);
                unsigned b1 = U(Wsm[(k0 + tig + 4) * WSTR + nb]);
                mma8(c[nt], a, b0, b1);
            }
        }
        #pragma unroll
        for (int nt = 0; nt < 4; ++nt) {
            int gcol = t * 128 + wxA * 32 + nt * 8 + 2 * tig;
            float bb0 = BQ[gcol], bb1 = BQ[gcol + 1];
            if (rA0 < NTOK) {
                float2 v; v.x = f2tf(c[nt][0] + bb0); v.y = f2tf(c[nt][1] + bb1);
                *(float2*)(QK + rA0 * QSTR + gcol) = v;
            }
            if (rA1 < NTOK) {
                float2 v; v.x = f2tf(c[nt][2] + bb0); v.y = f2tf(c[nt][3] + bb1);
                *(float2*)(QK + rA1 * QSTR + gcol) = v;
            }
        }
        __syncthreads();
    }

    // ---- Phase 2a: logits for ALL heads  (4 warps per head, M=64 N=56 K=32) ----
    const float scale = 0.17677669529663687f;   // 1/sqrt(32)
    {
        float* Lh = Ls + hB * LSH;
        const int qo = hB * 32;
        const int ko = 128 + qo;
        const int ntmax = wx2 ? 3 : 4;

        float c[2][4][4];
        #pragma unroll
        for (int mt = 0; mt < 2; ++mt)
            #pragma unroll
            for (int i = 0; i < 4; ++i)
                { c[mt][i][0]=0.f; c[mt][i][1]=0.f; c[mt][i][2]=0.f; c[mt][i][3]=0.f; }

        const int la0 = m0B + gid;
        const int la1 = m0B + 8 + gid;
        const int la2 = m0B + 16 + gid;
        int la3 = m0B + 24 + gid; if (la3 > 55) la3 = 55;

        #pragma unroll
        for (int ks = 0; ks < 4; ++ks) {
            int k0 = ks * 8;
            unsigned a0[4], a1[4];
            a0[0] = U(QK[la0 * QSTR + qo + k0 + tig]);
            a0[1] = U(QK[la1 * QSTR + qo + k0 + tig]);
            a0[2] = U(QK[la0 * QSTR + qo + k0 + tig + 4]);
            a0[3] = U(QK[la1 * QSTR + qo + k0 + tig + 4]);
            a1[0] = U(QK[la2 * QSTR + qo + k0 + tig]);
            a1[1] = U(QK[la3 * QSTR + qo + k0 + tig]);
            a1[2] = U(QK[la2 * QSTR + qo + k0 + tig + 4]);
            a1[3] = U(QK[la3 * QSTR + qo + k0 + tig + 4]);
            for (int nt = 0; nt < ntmax; ++nt) {
                int nb = wx2 * 32 + nt * 8 + gid;
                unsigned b0 = U(QK[nb * QSTR + ko + k0 + tig]);
                unsigned b1 = U(QK[nb * QSTR + ko + k0 + tig + 4]);
                mma8(c[0][nt], a0, b0, b1);
                mma8(c[1][nt], a1, b0, b1);
            }
        }

        #pragma unroll
        for (int mt = 0; mt < 2; ++mt) {
            int rs0 = m0B + mt * 16 + gid;
            int rs1 = rs0 + 8;
            int rn0 = rs0 / 7, cn0 = rs0 - rn0 * 7;
            int rn1 = rs1 / 7, cn1 = rs1 - rn1 * 7;
            for (int nt = 0; nt < ntmax; ++nt) {
                int col  = wx2 * 32 + nt * 8 + 2 * tig;
                int col1 = col + 1;
                int rm0 = col / 7,  cm0 = col  - rm0 * 7;
                int rm1 = col1 / 7, cm1 = col1 - rm1 * 7;
                if (rs0 < 56) {
                    float2 v;
                    v.x = (col  < NTOK) ? c[mt][nt][0] * scale + BT[rn0 - rm0 + 6] + BT[cn0 - cm0 + 6] : 0.f;
                    v.y = (col1 < NTOK) ? c[mt][nt][1] * scale + BT[rn0 - rm1 + 6] + BT[cn0 - cm1 + 6] : 0.f;
                    *(float2*)(Lh + rs0 * LSTR + col) = v;
                }
                if (rs1 < 56) {
                    float2 v;
                    v.x = (col  < NTOK) ? c[mt][nt][2] * scale + BT[rn1 - rm0 + 6] + BT[cn1 - cm0 + 6] : 0.f;
                    v.y = (col1 < NTOK) ? c[mt][nt][3] * scale + BT[rn1 - rm1 + 6] + BT[cn1 - cm1 + 6] : 0.f;
                    *(float2*)(Lh + rs1 * LSTR + col) = v;
                }
            }
        }
    }
    __syncthreads();

    // ---- Phase 2b: softmax, all heads (warp per row) ----
    #pragma unroll
    for (int h = 0; h < 4; ++h) {
        float* Lh = Ls + h * LSH;
        for (int row = ty; row < NTOK; row += 16) {
            float v0 = Lh[row * LSTR + tx];
            float v1 = (tx + 32 < NTOK) ? Lh[row * LSTR + tx + 32] : -1e30f;
            float mx = fmaxf(v0, v1);
            #pragma unroll
            for (int o = 16; o > 0; o >>= 1)
                mx = fmaxf(mx, __shfl_xor_sync(0xffffffffu, mx, o));
            float e0 = __expf(v0 - mx);
            float e1 = (tx + 32 < NTOK) ? __expf(v1 - mx) : 0.f;
            float s = e0 + e1;
            #pragma unroll
            for (int o = 16; o > 0; o >>= 1)
                s += __shfl_xor_sync(0xffffffffu, s, o);
            float inv = 1.0f / s;
            Lh[row * LSTR + tx] = f2tf(e0 * inv);
            if (tx + 32 < NTOK) Lh[row * LSTR + tx + 32] = f2tf(e1 * inv);
        }
    }
    __syncthreads();

    // ---- Phase 2c: out_h = attn @ V, all heads (4 warps/head, M=64 N=32 K=56) ----
    {
        float* Lh = Ls + hB * LSH;
        const int qo = hB * 32;
        const int vo = 256 + qo;

        float c[2][2][4];
        #pragma unroll
        for (int mt = 0; mt < 2; ++mt)
            #pragma unroll
            for (int i = 0; i < 2; ++i)
                { c[mt][i][0]=0.f; c[mt][i][1]=0.f; c[mt][i][2]=0.f; c[mt][i][3]=0.f; }

        const int la0 = m0B + gid;
        const int la1 = m0B + 8 + gid;
        const int la2 = m0B + 16 + gid;
        int la3 = m0B + 24 + gid; if (la3 > 55) la3 = 55;

        #pragma unroll
        for (int ks = 0; ks < 7; ++ks) {
            int k0 = ks * 8;
            unsigned a0[4], a1[4];
            a0[0] = U(Lh[la0 * LSTR + k0 + tig]);
            a0[1] = U(Lh[la1 * LSTR + k0 + tig]);
            a0[2] = U(Lh[la0 * LSTR + k0 + tig + 4]);
            a0[3] = U(Lh[la1 * LSTR + k0 + tig + 4]);
            a1[0] = U(Lh[la2 * LSTR + k0 + tig]);
            a1[1] = U(Lh[la3 * LSTR + k0 + tig]);
            a1[2] = U(Lh[la2 * LSTR + k0 + tig + 4]);
            a1[3] = U(Lh[la3 * LSTR + k0 + tig + 4]);
            #pragma unroll
            for (int nt = 0; nt < 2; ++nt) {
                int db = wx2 * 16 + nt * 8 + gid;
                unsigned b0 = U(QK[(k0 + tig) * QSTR + vo + db]);
                unsigned b1 = U(QK[(k0 + tig + 4) * QSTR + vo + db]);
                mma8(c[0][nt], a0, b0, b1);
                mma8(c[1][nt], a1, b0, b1);
            }
        }
        #pragma unroll
        for (int mt = 0; mt < 2; ++mt) {
            int rs0 = m0B + mt * 16 + gid;
            int rs1 = rs0 + 8;
            #pragma unroll
            for (int nt = 0; nt < 2; ++nt) {
                int col = qo + wx2 * 16 + nt * 8 + 2 * tig;
                if (rs0 < NTOK) {
                    float2 v; v.x = f2tf(c[mt][nt][0]); v.y = f2tf(c[mt][nt][1]);
                    *(float2*)(Xs + rs0 * XSTR + col) = v;
                }
                if (rs1 < NTOK) {
                    float2 v; v.x = f2tf(c[mt][nt][2]); v.y = f2tf(c[mt][nt][3]);
                    *(float2*)(Xs + rs1 * XSTR + col) = v;
                }
            }
        }
    }
    __syncthreads();

    // ---- Phase 3: load w_proj (Ls region is free now), then proj GEMM ----
    for (int idx = tid; idx < 128 * 32; idx += 512) {
        int k = idx >> 5, c4 = idx & 31;
        float4 g = *(const float4*)(w_proj + (long)k * 128 + c4 * 4);
        g.x = f2tf(g.x); g.y = f2tf(g.y); g.z = f2tf(g.z); g.w = f2tf(g.w);
        *(float4*)(Wsm + k * WSTR + c4 * 4) = g;
    }
    __syncthreads();

    {
        float c[4][4];
        #pragma unroll
        for (int i = 0; i < 4; ++i) { c[i][0]=0.f; c[i][1]=0.f; c[i][2]=0.f; c[i][3]=0.f; }

        #pragma unroll 4
        for (int kk = 0; kk < 16; ++kk) {
            int k0 = kk * 8;
            unsigned a[4];
            a[0] = U(Xs[rA0 * XSTR + k0 + tig]);
            a[1] = U(Xs[aA1 * XSTR + k0 + tig]);
            a[2] = U(Xs[rA0 * XSTR + k0 + tig + 4]);
            a[3] = U(Xs[aA1 * XSTR + k0 + tig + 4]);
            #pragma unroll
            for (int nt = 0; nt < 4; ++nt) {
                int nb = wxA * 32 + nt * 8 + gid;
                unsigned b0 = U(Wsm[(k0 + tig) * WSTR + nb]);
                unsigned b1 = U(Wsm[(k0 + tig + 4) * WSTR + nb]);
                mma8(c[nt], a, b0, b1);
            }
        }

        long base0 = 0, base1 = 0;
        if (rA0 < NTOK) {
            int i = rA0 / 7, j = rA0 - (rA0 / 7) * 7;
            base0 = (((long)bz * HW + wh * WSZ + i) * HW + ww * WSZ + j) * 128;
        }
        if (rA1 < NTOK) {
            int i = rA1 / 7, j = rA1 - (rA1 / 7) * 7;
            base1 = (((long)bz * HW + wh * WSZ + i) * HW + ww * WSZ + j) * 128;
        }
        #pragma unroll
        for (int nt = 0; nt < 4; ++nt) {
            int col = wxA * 32 + nt * 8 + 2 * tig;
            float bb0 = BP[col], bb1 = BP[col + 1];
            if (rA0 < NTOK) {
                float2 v; v.x = c[nt][0] + bb0; v.y = c[nt][1] + bb1;
                *(float2*)(out + base0 + col) = v;
            }
            if (rA1 < NTOK) {
                float2 v; v.x = c[nt][2] + bb0; v.y = c[nt][3] + bb1;
                *(float2*)(out + base1 + col) = v;
            }
        }
    }
}

extern "C" void kernel_launch(void* const* d_in, const int* in_sizes, int n_in,
                              void* d_out, int out_size) {
    const float* x          = (const float*)d_in[0];
    const float* w_qkv      = (const float*)d_in[1];
    const float* b_qkv      = (const float*)d_in[2];
    const float* w_proj     = (const float*)d_in[3];
    const float* b_proj     = (const float*)d_in[4];
    const float* bias_table = (const float*)d_in[5];
    float* out = (float*)d_out;
    (void)in_sizes; (void)n_in; (void)out_size;

    cudaFuncSetAttribute(win_attn_mma16_kernel,
                         cudaFuncAttributeMaxDynamicSharedMemorySize, SMEM_BYTES);

    dim3 grid(NWIN, NWIN, 4);
    win_attn_mma16_kernel<<<grid, 512, SMEM_BYTES>>>(
        x, w_qkv, b_qkv, w_proj, b_proj, bias_table, out);
}